// round 3
// baseline (speedup 1.0000x reference)
#include <cuda_runtime.h>

#define FDIM 128
#define F4   32            // FDIM/4
#define BMAX 2048
#define NMAX 1100000
#define EPSC 1e-3f

// ---- scratch (device globals; no allocations allowed) ----
__device__ int   g_is64;           // 1 if graph_id buffer is int64, 0 if int32
__device__ int   g_counts[BMAX];
__device__ int   g_offsets[BMAX + 1];
__device__ int   g_cursor[BMAX];
__device__ int   g_perm[NMAX];
__device__ float g_scale[BMAX * FDIM];
__device__ float g_shift[BMAX * FDIM];

__device__ __forceinline__ int load_gid(const void* gid, int i, int is64, int B) {
    int g = is64 ? (int)((const long long*)gid)[i] : ((const int*)gid)[i];
    // defensive clamp: never fault on unexpected data
    return (g < 0) ? 0 : (g >= B ? B - 1 : g);
}

// ---- pass 0: probe gid dtype + zero counters ----
__global__ void gn_init_kernel(const void* gid, int N, int B) {
    __shared__ int bad;
    if (threadIdx.x == 0) bad = 0;
    __syncthreads();
    // Interpret as int64; if any of the first `probe` values is out of range,
    // the buffer is int32. (int32 data viewed as int64 -> huge values w.h.p.)
    int probe = N / 2;
    if (probe > 4096) probe = 4096;
    const long long* g64 = (const long long*)gid;
    for (int i = threadIdx.x; i < probe; i += blockDim.x) {
        long long v = g64[i];
        if (v < 0 || v >= (long long)B) bad = 1;
    }
    __syncthreads();
    if (threadIdx.x == 0) g_is64 = bad ? 0 : 1;
    for (int i = threadIdx.x; i < B; i += blockDim.x) g_counts[i] = 0;
}

// ---- pass 1: histogram of graph_id (smem-aggregated) ----
__global__ __launch_bounds__(256) void gn_hist_kernel(const void* __restrict__ gid,
                                                      int N, int B) {
    __shared__ int sh[BMAX];
    for (int i = threadIdx.x; i < B; i += blockDim.x) sh[i] = 0;
    __syncthreads();
    int is64 = g_is64;
    for (int i = blockIdx.x * blockDim.x + threadIdx.x; i < N;
         i += gridDim.x * blockDim.x) {
        atomicAdd(&sh[load_gid(gid, i, is64, B)], 1);
    }
    __syncthreads();
    for (int i = threadIdx.x; i < B; i += blockDim.x) {
        int v = sh[i];
        if (v) atomicAdd(&g_counts[i], v);
    }
}

// ---- pass 2: exclusive scan over counts -> offsets, cursor ----
__global__ void gn_scan_kernel(int B) {
    __shared__ int sh[BMAX];
    for (int i = threadIdx.x; i < B; i += blockDim.x) sh[i] = g_counts[i];
    __syncthreads();
    if (threadIdx.x == 0) {
        int acc = 0;
        for (int i = 0; i < B; i++) {
            int c = sh[i];
            sh[i] = acc;
            acc += c;
        }
        g_offsets[B] = acc;
    }
    __syncthreads();
    for (int i = threadIdx.x; i < B; i += blockDim.x) {
        g_offsets[i] = sh[i];
        g_cursor[i]  = sh[i];
    }
}

// ---- pass 3: scatter node indices into per-graph contiguous segments ----
__global__ __launch_bounds__(256) void gn_scatter_kernel(const void* __restrict__ gid,
                                                         int N, int B) {
    int is64 = g_is64;
    for (int i = blockIdx.x * blockDim.x + threadIdx.x; i < N;
         i += gridDim.x * blockDim.x) {
        int g   = load_gid(gid, i, is64, B);
        int pos = atomicAdd(&g_cursor[g], 1);
        if (pos >= 0 && pos < NMAX) g_perm[pos] = i;
    }
}

// ---- pass 4: per-graph moments -> scale/shift (1 CTA per graph, 8 warps) ----
__global__ __launch_bounds__(256) void gn_stats_kernel(const float* __restrict__ values,
                                                       const float* __restrict__ gamma,
                                                       const float* __restrict__ beta,
                                                       const float* __restrict__ alpha) {
    int b     = blockIdx.x;
    int start = g_offsets[b];
    int end   = g_offsets[b + 1];
    int c     = end - start;
    int w     = threadIdx.x >> 5;
    int lane  = threadIdx.x & 31;

    const float4* v4 = (const float4*)values;

    float4 s = make_float4(0.f, 0.f, 0.f, 0.f);
    float4 q = make_float4(0.f, 0.f, 0.f, 0.f);

    // warp w handles rows start+w, start+w+8, ... ; lane owns features [4*lane, 4*lane+3]
    for (int r = start + w; r < end; r += 8) {
        int node = g_perm[r];
        float4 v = __ldg(&v4[(size_t)node * F4 + lane]);
        s.x += v.x; s.y += v.y; s.z += v.z; s.w += v.w;
        q.x = fmaf(v.x, v.x, q.x);
        q.y = fmaf(v.y, v.y, q.y);
        q.z = fmaf(v.z, v.z, q.z);
        q.w = fmaf(v.w, v.w, q.w);
    }

    __shared__ float4 ss[8][F4];
    __shared__ float4 sq[8][F4];
    ss[w][lane] = s;
    sq[w][lane] = q;
    __syncthreads();

    int f = threadIdx.x;
    if (f < FDIM) {
        const float* ssf = (const float*)ss;   // layout [8][128] floats
        const float* sqf = (const float*)sq;
        float S = 0.f, Q = 0.f;
#pragma unroll
        for (int i = 0; i < 8; i++) {
            S += ssf[i * FDIM + f];
            Q += sqf[i * FDIM + f];
        }
        float inv  = (c > 0) ? (1.0f / (float)c) : 0.0f;
        float m    = S * inv;
        float m2   = Q * inv;
        float msh  = m * alpha[f];                       // shifted mean
        float var  = m2 - 2.0f * msh * m + msh * msh;    // E[(x - msh)^2]
        float rstd = rsqrtf(var + EPSC);
        float sc   = gamma[f] * rstd;
        g_scale[b * FDIM + f] = sc;
        g_shift[b * FDIM + f] = beta[f] - msh * sc;
    }
}

// ---- pass 5: normalize, streaming in natural node order (warp-per-row) ----
__global__ __launch_bounds__(256) void gn_norm_kernel(const float* __restrict__ values,
                                                      const void* __restrict__ gid,
                                                      float* __restrict__ out,
                                                      int N, int B) {
    int w    = threadIdx.x >> 5;       // warp within CTA (0..7)
    int lane = threadIdx.x & 31;
    int rows_per_step = gridDim.x * 8;
    int is64 = g_is64;

    const float4* v4  = (const float4*)values;
    const float4* sc4 = (const float4*)g_scale;
    const float4* sh4 = (const float4*)g_shift;
    float4*       o4  = (float4*)out;

    for (int node = blockIdx.x * 8 + w; node < N; node += rows_per_step) {
        int    b   = load_gid(gid, node, is64, B);
        size_t idx = (size_t)node * F4 + lane;
        float4 v  = __ldg(&v4[idx]);
        float4 sc = __ldg(&sc4[b * F4 + lane]);
        float4 sh = __ldg(&sh4[b * F4 + lane]);
        float4 o;
        o.x = fmaf(v.x, sc.x, sh.x);
        o.y = fmaf(v.y, sc.y, sh.y);
        o.z = fmaf(v.z, sc.z, sh.z);
        o.w = fmaf(v.w, sc.w, sh.w);
        o4[idx] = o;
    }
}

extern "C" void kernel_launch(void* const* d_in, const int* in_sizes, int n_in,
                              void* d_out, int out_size) {
    const float* values = (const float*)d_in[0];
    const void*  gid    = d_in[1];
    // d_in[2] = reference_ids (only its length B is needed)
    const float* gamma  = (const float*)d_in[3];
    const float* beta   = (const float*)d_in[4];
    const float* alpha  = (const float*)d_in[5];

    int N = in_sizes[0] / FDIM;
    int B = in_sizes[2];
    if (B > BMAX) B = BMAX;
    if (B < 1)    B = 1;

    gn_init_kernel<<<1, 256>>>(gid, N, B);
    gn_hist_kernel<<<592, 256>>>(gid, N, B);
    gn_scan_kernel<<<1, 1024>>>(B);
    gn_scatter_kernel<<<1024, 256>>>(gid, N, B);
    gn_stats_kernel<<<B, 256>>>(values, gamma, beta, alpha);
    gn_norm_kernel<<<2432, 256>>>(values, gid, (float*)d_out, N, B);
}